// round 8
// baseline (speedup 1.0000x reference)
#include <cuda_runtime.h>
#include <cuda_bf16.h>
#include <cstdint>

#define N_NODES 100000
#define N_EDGES 1000000
#define D 64

typedef unsigned long long u64;

// ---------------------------------------------------------------------------
// Scratch. g_count starts zero (device globals zero-init) and every
// kernel_launch leaves it zero (scan resets it) -> no zero kernel.
// ---------------------------------------------------------------------------
__device__ float g_agg[N_NODES * D];
__device__ int   g_count[N_NODES];
__device__ int   g_off[N_NODES];
__device__ int   g_end[N_NODES];
__device__ int   g_cur[N_NODES];
__device__ int   g_src[N_EDGES];
__device__ int   g_base;

// ---------------------------------------------------------------------------
// K0: histogram of dst — 4 edges per thread (int4 load, 4 indep atomics)
// ---------------------------------------------------------------------------
__global__ void hist_kernel(const int4* __restrict__ dst4,
                            int* __restrict__ cnt,
                            int* __restrict__ base) {
    int t = blockIdx.x * blockDim.x + threadIdx.x;
    if (t == 0) *base = 0;
    if (t < N_EDGES / 4) {
        int4 d = dst4[t];
        if ((unsigned)d.x < N_NODES) atomicAdd(&cnt[d.x], 1);
        if ((unsigned)d.y < N_NODES) atomicAdd(&cnt[d.y], 1);
        if ((unsigned)d.z < N_NODES) atomicAdd(&cnt[d.z], 1);
        if ((unsigned)d.w < N_NODES) atomicAdd(&cnt[d.w], 1);
    }
}

// ---------------------------------------------------------------------------
// K1: block scan + atomic base -> off/end/cur; reset cnt.
// ---------------------------------------------------------------------------
#define SCAN_BLK 256
#define N_SBLKS ((N_NODES + SCAN_BLK - 1) / SCAN_BLK)

__global__ __launch_bounds__(SCAN_BLK)
void scan_atomic_kernel(int* __restrict__ cnt, int* __restrict__ off,
                        int* __restrict__ endp, int* __restrict__ cur,
                        int* __restrict__ base) {
    __shared__ int sm[SCAN_BLK];
    __shared__ int sbase;
    int i = blockIdx.x * SCAN_BLK + threadIdx.x;
    int t = threadIdx.x;
    int v = (i < N_NODES) ? cnt[i] : 0;
    sm[t] = v;
    for (int ofs = 1; ofs < SCAN_BLK; ofs <<= 1) {
        __syncthreads();
        int u = (t >= ofs) ? sm[t - ofs] : 0;
        __syncthreads();
        sm[t] += u;
    }
    __syncthreads();
    if (t == SCAN_BLK - 1) sbase = atomicAdd(base, sm[SCAN_BLK - 1]);
    __syncthreads();
    if (i < N_NODES) {
        int incl = sbase + sm[t];
        int st = incl - v;
        off[i]  = st;
        cur[i]  = st;
        endp[i] = incl;
        cnt[i]  = 0;
    }
}

// ---------------------------------------------------------------------------
// K2: fill CSR src lists — 4 edges per thread (2x int4 loads, 4 indep chains)
// ---------------------------------------------------------------------------
__global__ void fill_kernel(const int4* __restrict__ src4,
                            const int4* __restrict__ dst4,
                            int* __restrict__ cur,
                            int* __restrict__ csr_src) {
    int t = blockIdx.x * blockDim.x + threadIdx.x;
    if (t < N_EDGES / 4) {
        int4 s = src4[t];
        int4 d = dst4[t];
        if ((unsigned)s.x < N_NODES && (unsigned)d.x < N_NODES)
            csr_src[atomicAdd(&cur[d.x], 1)] = s.x;
        if ((unsigned)s.y < N_NODES && (unsigned)d.y < N_NODES)
            csr_src[atomicAdd(&cur[d.y], 1)] = s.y;
        if ((unsigned)s.z < N_NODES && (unsigned)d.z < N_NODES)
            csr_src[atomicAdd(&cur[d.z], 1)] = s.z;
        if ((unsigned)s.w < N_NODES && (unsigned)d.w < N_NODES)
            csr_src[atomicAdd(&cur[d.w], 1)] = s.w;
    }
}

// ---------------------------------------------------------------------------
// K3: gather + fused (1+eps)*x, float4 edition.
// One warp per node. half = lane>>4, hl = lane&15: lane owns float4 col hl,
// half-warp 0/1 process neighbors j+0 / j+1 of each pair -> one LDG.128
// serves 2 neighbors; 2 pairs in flight per unrolled step. Halves combined
// at the end via shfl_xor(16).
// ---------------------------------------------------------------------------
__global__ __launch_bounds__(256)
void gather_kernel(const float4* __restrict__ x4,
                   const float* __restrict__ eps,
                   const int* __restrict__ off,
                   const int* __restrict__ endp,
                   const int* __restrict__ csr_src,
                   float4* __restrict__ agg4) {
    int warp = (blockIdx.x * blockDim.x + threadIdx.x) >> 5;
    int lane = threadIdx.x & 31;
    if (warp >= N_NODES) return;
    const int half = lane >> 4;     // 0 or 1
    const int hl   = lane & 15;     // float4 index within row

    float4 acc = make_float4(0.f, 0.f, 0.f, 0.f);
    if (half == 0) {
        float s = 1.0f + *eps;
        float4 v = x4[(unsigned)warp * 16u + hl];
        acc.x = s * v.x; acc.y = s * v.y; acc.z = s * v.z; acc.w = s * v.w;
    }

    int start = off[warp];
    int end   = endp[warp];

    for (int base = start; base < end; base += 32) {
        int n = min(32, end - base);
        int myidx = (lane < n) ? csr_src[base + lane] : 0;
        for (int j = 0; j < n; j += 4) {
            // pair A: neighbors j, j+1; pair B: neighbors j+2, j+3
            int sA = __shfl_sync(0xffffffffu, myidx, j + half);
            int sB = __shfl_sync(0xffffffffu, myidx, j + 2 + half);
            bool vA = (j + half) < n;
            bool vB = (j + 2 + half) < n;
            if (vA) {
                float4 a = x4[(unsigned)sA * 16u + hl];
                acc.x += a.x; acc.y += a.y; acc.z += a.z; acc.w += a.w;
            }
            if (vB) {
                float4 b = x4[(unsigned)sB * 16u + hl];
                acc.x += b.x; acc.y += b.y; acc.z += b.z; acc.w += b.w;
            }
        }
    }

    // combine halves
    acc.x += __shfl_xor_sync(0xffffffffu, acc.x, 16);
    acc.y += __shfl_xor_sync(0xffffffffu, acc.y, 16);
    acc.z += __shfl_xor_sync(0xffffffffu, acc.z, 16);
    acc.w += __shfl_xor_sync(0xffffffffu, acc.w, 16);

    if (half == 0)
        agg4[(unsigned)warp * 16u + hl] = acc;
}

// ---------------------------------------------------------------------------
// K4: fused 2-layer MLP (unchanged from R7 — conflict-free quads, FMA2)
// ---------------------------------------------------------------------------
#define MLP_ROWS 64
#define MLP_THREADS 128
#define XS_STRIDE 66

__device__ __forceinline__ float leaky(float v) {
    return fmaxf(v, 0.01f * v);
}

#define FMA2(d, a, b, c) \
    asm("fma.rn.f32x2 %0, %1, %2, %3;" : "=l"(d) : "l"(a), "l"(b), "l"(c))
#define PACK_DUP(out, f) \
    asm("mov.b64 %0, {%1, %1};" : "=l"(out) : "r"(__float_as_uint(f)))
#define PACK2F(out, lo, hi) \
    asm("mov.b64 %0, {%1, %2};" : "=l"(out) : "r"(__float_as_uint(lo)), "r"(__float_as_uint(hi)))
#define UNPACK2F(lo, hi, in) \
    { unsigned _l, _h; asm("mov.b64 {%0, %1}, %2;" : "=r"(_l), "=r"(_h) : "l"(in)); \
      lo = __uint_as_float(_l); hi = __uint_as_float(_h); }

__global__ __launch_bounds__(MLP_THREADS)
void mlp_kernel(const float* __restrict__ agg,
                const float* __restrict__ W1, const float* __restrict__ b1,
                const float* __restrict__ W2, const float* __restrict__ b2,
                float* __restrict__ out) {
    __shared__ float Xs[MLP_ROWS][XS_STRIDE];
    __shared__ float Ws[D][D];
    __shared__ float bs[D];

    const int tid = threadIdx.x;
    const int cg  = tid & 7;
    const int rg  = tid >> 3;
    const int row_base = blockIdx.x * MLP_ROWS;
    const int r0 = rg * 4;
    const int ca = cg * 4;
    const int cb = 32 + cg * 4;

    {
        const float2* src = (const float2*)(agg + (long long)row_base * D);
        for (int idx = tid; idx < MLP_ROWS * (D / 2); idx += MLP_THREADS) {
            int r = idx >> 5;
            int p = idx & 31;
            float2 v;
            if (row_base + r < N_NODES) v = src[r * 32 + p];
            else { v.x = 0.f; v.y = 0.f; }
            Xs[r][p * 2]     = v.x;
            Xs[r][p * 2 + 1] = v.y;
        }
    }
    {
        const float4* w = (const float4*)W1;
        float4* ws = (float4*)&Ws[0][0];
        for (int idx = tid; idx < D * D / 4; idx += MLP_THREADS) ws[idx] = w[idx];
        if (tid < D) bs[tid] = b1[tid];
    }
    __syncthreads();

    u64 acc[4][4];
    {
        u64 a0, a1, b0, b1p;
        PACK2F(a0, bs[ca],     bs[ca + 1]);
        PACK2F(a1, bs[ca + 2], bs[ca + 3]);
        PACK2F(b0, bs[cb],     bs[cb + 1]);
        PACK2F(b1p, bs[cb + 2], bs[cb + 3]);
        #pragma unroll
        for (int i = 0; i < 4; i++) {
            acc[i][0] = a0; acc[i][1] = a1; acc[i][2] = b0; acc[i][3] = b1p;
        }
    }

    #pragma unroll 4
    for (int k = 0; k < D; k++) {
        ulonglong2 wa = *(const ulonglong2*)&Ws[k][ca];
        ulonglong2 wb = *(const ulonglong2*)&Ws[k][cb];
        #pragma unroll
        for (int i = 0; i < 4; i++) {
            u64 xx; PACK_DUP(xx, Xs[r0 + i][k]);
            FMA2(acc[i][0], xx, wa.x, acc[i][0]);
            FMA2(acc[i][1], xx, wa.y, acc[i][1]);
            FMA2(acc[i][2], xx, wb.x, acc[i][2]);
            FMA2(acc[i][3], xx, wb.y, acc[i][3]);
        }
    }
    __syncthreads();

    #pragma unroll
    for (int i = 0; i < 4; i++) {
        float lo, hi;
        UNPACK2F(lo, hi, acc[i][0]); Xs[r0 + i][ca]     = leaky(lo); Xs[r0 + i][ca + 1] = leaky(hi);
        UNPACK2F(lo, hi, acc[i][1]); Xs[r0 + i][ca + 2] = leaky(lo); Xs[r0 + i][ca + 3] = leaky(hi);
        UNPACK2F(lo, hi, acc[i][2]); Xs[r0 + i][cb]     = leaky(lo); Xs[r0 + i][cb + 1] = leaky(hi);
        UNPACK2F(lo, hi, acc[i][3]); Xs[r0 + i][cb + 2] = leaky(lo); Xs[r0 + i][cb + 3] = leaky(hi);
    }

    {
        const float4* w = (const float4*)W2;
        float4* ws = (float4*)&Ws[0][0];
        for (int idx = tid; idx < D * D / 4; idx += MLP_THREADS) ws[idx] = w[idx];
        if (tid < D) bs[tid] = b2[tid];
    }
    __syncthreads();

    {
        u64 a0, a1, b0, b1p;
        PACK2F(a0, bs[ca],     bs[ca + 1]);
        PACK2F(a1, bs[ca + 2], bs[ca + 3]);
        PACK2F(b0, bs[cb],     bs[cb + 1]);
        PACK2F(b1p, bs[cb + 2], bs[cb + 3]);
        #pragma unroll
        for (int i = 0; i < 4; i++) {
            acc[i][0] = a0; acc[i][1] = a1; acc[i][2] = b0; acc[i][3] = b1p;
        }
    }

    #pragma unroll 4
    for (int k = 0; k < D; k++) {
        ulonglong2 wa = *(const ulonglong2*)&Ws[k][ca];
        ulonglong2 wb = *(const ulonglong2*)&Ws[k][cb];
        #pragma unroll
        for (int i = 0; i < 4; i++) {
            u64 xx; PACK_DUP(xx, Xs[r0 + i][k]);
            FMA2(acc[i][0], xx, wa.x, acc[i][0]);
            FMA2(acc[i][1], xx, wa.y, acc[i][1]);
            FMA2(acc[i][2], xx, wb.x, acc[i][2]);
            FMA2(acc[i][3], xx, wb.y, acc[i][3]);
        }
    }

    #pragma unroll
    for (int i = 0; i < 4; i++) {
        int row = row_base + r0 + i;
        if (row < N_NODES) {
            float lo, hi;
            float4 va, vb;
            UNPACK2F(lo, hi, acc[i][0]); va.x = leaky(lo); va.y = leaky(hi);
            UNPACK2F(lo, hi, acc[i][1]); va.z = leaky(lo); va.w = leaky(hi);
            UNPACK2F(lo, hi, acc[i][2]); vb.x = leaky(lo); vb.y = leaky(hi);
            UNPACK2F(lo, hi, acc[i][3]); vb.z = leaky(lo); vb.w = leaky(hi);
            *(float4*)(out + (long long)row * D + ca) = va;
            *(float4*)(out + (long long)row * D + cb) = vb;
        }
    }
}

// ---------------------------------------------------------------------------
// launch
// ---------------------------------------------------------------------------
extern "C" void kernel_launch(void* const* d_in, const int* in_sizes, int n_in,
                              void* d_out, int out_size) {
    const float* x   = (const float*)d_in[0];
    const int*   ei  = (const int*)d_in[1];      // int32 (JAX downcasts int64)
    const float* eps = (const float*)d_in[2];
    const float* W1  = (const float*)d_in[3];
    const float* b1  = (const float*)d_in[4];
    const float* W2  = (const float*)d_in[5];
    const float* b2  = (const float*)d_in[6];
    float* out = (float*)d_out;

    float* agg;  cudaGetSymbolAddress((void**)&agg,  g_agg);
    int*   cnt;  cudaGetSymbolAddress((void**)&cnt,  g_count);
    int*   off;  cudaGetSymbolAddress((void**)&off,  g_off);
    int*   endp; cudaGetSymbolAddress((void**)&endp, g_end);
    int*   cur;  cudaGetSymbolAddress((void**)&cur,  g_cur);
    int*   csrs; cudaGetSymbolAddress((void**)&csrs, g_src);
    int*   base; cudaGetSymbolAddress((void**)&base, g_base);

    const int4* src4 = (const int4*)ei;
    const int4* dst4 = (const int4*)(ei + N_EDGES);
    const int EQ = N_EDGES / 4;

    hist_kernel<<<(EQ + 255) / 256, 256>>>(dst4, cnt, base);               // #0
    scan_atomic_kernel<<<N_SBLKS, SCAN_BLK>>>(cnt, off, endp, cur, base);  // #1
    fill_kernel<<<(EQ + 255) / 256, 256>>>(src4, dst4, cur, csrs);         // #2
    gather_kernel<<<(N_NODES + 7) / 8, 256>>>((const float4*)x, eps,       // #3
                                              off, endp, csrs, (float4*)agg);
    mlp_kernel<<<(N_NODES + MLP_ROWS - 1) / MLP_ROWS, MLP_THREADS>>>(      // #4
        agg, W1, b1, W2, b2, out);
}